// round 14
// baseline (speedup 1.0000x reference)
#include <cuda_runtime.h>
#include <math.h>

#define STEPS 9
#define NBATCH 2048

// ---------------- packed pair weights (device globals; no allocation) ----
// layout: [(cpair*9 + k) * O + o] as float2
__device__ float2 g_p_conv0[128 * 9 * 128];  // C=256 -> 128 cp, O=128
__device__ float2 g_p_conv1[ 64 * 9 * 128];  // C=128 -> 64 cp,  O=128
// cx0 cp order: cp0..63 = x channel pairs; cp64 = (ch130 v_first, 0); cp65 = (v_p2, v_p1)
__device__ float2 g_p_cx0 [ 66 * 9 * 256];
__device__ float2 g_p_ch0 [ 32 * 9 * 256];
__device__ float2 g_p_cx1 [ 32 * 9 * 256];
__device__ float2 g_p_ch1 [ 32 * 9 * 256];
__device__ float2 g_p_fc  [ 50 * 1568];          // fc pair-packed: [o][cp*49+p]
// per-sample scratch (global to allow 2 CTAs/SM)
__device__ float g_gxc[(size_t)NBATCH * 12544];  // const gates, TRANSPOSED [i*256+o]
__device__ float g_c  [(size_t)NBATCH * 6272];   // c0 (3136) + c1 (3136)

__global__ void pack_weights(const float* __restrict__ w0, const float* __restrict__ w1,
                             const float* __restrict__ wcx0, const float* __restrict__ wch0,
                             const float* __restrict__ wcx1, const float* __restrict__ wch1,
                             const float* __restrict__ fcw)
{
    int i = blockIdx.x * blockDim.x + threadIdx.x;
    const int s0 = 128 * 9 * 128, s1 = 64 * 9 * 128, s2 = 66 * 9 * 256, s3 = 32 * 9 * 256;
    if (i < s0) {
        int o = i % 128, ck = i / 128, cp = ck / 9, k = ck % 9;
        g_p_conv0[i] = make_float2(w0[(o * 256 + 2 * cp) * 9 + k],
                                   w0[(o * 256 + 2 * cp + 1) * 9 + k]);
        return;
    }
    i -= s0;
    if (i < s1) {
        int o = i % 128, ck = i / 128, cp = ck / 9, k = ck % 9;
        g_p_conv1[i] = make_float2(w1[(o * 128 + 2 * cp) * 9 + k],
                                   w1[(o * 128 + 2 * cp + 1) * 9 + k]);
        return;
    }
    i -= s1;
    if (i < s2) {
        int o = i % 256, ck = i / 256, cp = ck / 9, k = ck % 9;
        float a, b;
        if (cp < 64)      { a = wcx0[(o * 131 + 2 * cp) * 9 + k];
                            b = wcx0[(o * 131 + 2 * cp + 1) * 9 + k]; }
        else if (cp == 64){ a = wcx0[(o * 131 + 130) * 9 + k]; b = 0.0f; }
        else              { a = wcx0[(o * 131 + 128) * 9 + k];
                            b = wcx0[(o * 131 + 129) * 9 + k]; }
        g_p_cx0[i] = make_float2(a, b);
        return;
    }
    i -= s2;
    if (i < s3) {
        int o = i % 256, ck = i / 256, cp = ck / 9, k = ck % 9;
        g_p_ch0[i] = make_float2(wch0[(o * 64 + 2 * cp) * 9 + k],
                                 wch0[(o * 64 + 2 * cp + 1) * 9 + k]);
        return;
    }
    i -= s3;
    if (i < s3) {
        int o = i % 256, ck = i / 256, cp = ck / 9, k = ck % 9;
        g_p_cx1[i] = make_float2(wcx1[(o * 64 + 2 * cp) * 9 + k],
                                 wcx1[(o * 64 + 2 * cp + 1) * 9 + k]);
        return;
    }
    i -= s3;
    if (i < s3) {
        int o = i % 256, ck = i / 256, cp = ck / 9, k = ck % 9;
        g_p_ch1[i] = make_float2(wch1[(o * 64 + 2 * cp) * 9 + k],
                                 wch1[(o * 64 + 2 * cp + 1) * 9 + k]);
        return;
    }
    i -= s3;
    if (i < 50 * 1568) {
        int o = i / 1568, e = i % 1568, cp = e / 49, p = e % 49;
        g_p_fc[i] = make_float2(fcw[o * 3136 + (2 * cp) * 49 + p],
                                fcw[o * 3136 + (2 * cp + 1) * 49 + p]);
        return;
    }
}

// ---------------- packed fp32x2 helpers ----------------
__device__ __forceinline__ void ffma2(unsigned long long& d, unsigned long long a,
                                      unsigned long long b)
{
    asm("fma.rn.f32x2 %0, %1, %2, %0;" : "+l"(d) : "l"(a), "l"(b));
}
__device__ __forceinline__ unsigned long long pack2(float lo, float hi)
{
    unsigned long long r;
    asm("mov.b64 %0, {%1, %2};" : "=l"(r) : "f"(lo), "f"(hi));
    return r;
}
__device__ __forceinline__ float fold2(unsigned long long v)
{
    float lo, hi;
    asm("mov.b64 {%0, %1}, %2;" : "=f"(lo), "=f"(hi) : "l"(v));
    return lo + hi;
}
// padded pair-plane pixel address (floats): rows padded to 10 u64 (20 floats)
__device__ __forceinline__ int pidx(int p)
{
    return ((p / 7 + 1) * 10 + (p % 7) + 1) * 2;
}
__device__ __forceinline__ int pidx64(int p)   // u64-granular index
{
    return (p / 7 + 1) * 10 + (p % 7) + 1;
}
__device__ __forceinline__ float sigm(float v) { return 1.0f / (1.0f + expf(-v)); }
// warp-uniform gate activation: gates i(0), f(1), o(3) -> sigmoid; g(2) -> tanh
__device__ __forceinline__ float gact(int gate, float v)
{
    return (gate == 2) ? tanhf(v) : 1.0f / (1.0f + expf(-v));
}

// 3x3 SAME conv over channel-pair-interleaved padded planes (u64 = float pair).
// plane: [cp][9 rows x 10 u64]; input-row-major, zero-register weight pipeline.
// Per-acc term order: (ky 0,1,2)x(kx 0,1,2) per cp — identical to prior rounds.
template <int NR, int R0, int OS>
__device__ __forceinline__ void conv_rm(const float2* __restrict__ W, const int CP,
                                        const float* __restrict__ plane,
                                        const int o, unsigned long long* acc)
{
    const unsigned long long* pb = (const unsigned long long*)plane + R0 * 10;
    const unsigned long long* wptr = (const unsigned long long*)W + o;

    unsigned long long wA[9];
#pragma unroll
    for (int k = 0; k < 9; ++k) wA[k] = __ldg(wptr + k * OS);

    for (int cp = 0; cp < CP; ++cp) {
        const unsigned long long* wnext = (cp + 1 < CP) ? wptr + 9 * OS : wptr;

#pragma unroll
        for (int ri = 0; ri < NR + 2; ++ri) {          // input row R0 + ri
            unsigned long long row[9];
            const ulonglong2* rp = (const ulonglong2*)(pb + ri * 10);
#pragma unroll
            for (int j = 0; j < 4; ++j) {
                ulonglong2 q = rp[j];
                row[2 * j] = q.x;
                row[2 * j + 1] = q.y;
            }
            row[8] = (pb + ri * 10)[8];
#pragma unroll
            for (int ky = 0; ky < 3; ++ky) {
                const int ry = ri - ky;
                if (ry >= 0 && ry < NR) {
#pragma unroll
                    for (int kx = 0; kx < 3; ++kx) {
                        const unsigned long long wv = wA[ky * 3 + kx];
#pragma unroll
                        for (int x = 0; x < 7; ++x)
                            ffma2(acc[ry * 7 + x], wv, row[x + kx]);
                    }
                }
            }
            if (ri == NR - 1) {
#pragma unroll
                for (int k = 0; k < 3; ++k) wA[k] = __ldg(wnext + k * OS);
            }
            if (ri == NR) {
#pragma unroll
                for (int k = 3; k < 6; ++k) wA[k] = __ldg(wnext + k * OS);
            }
            if (ri == NR + 1) {
#pragma unroll
                for (int k = 6; k < 9; ++k) wA[k] = __ldg(wnext + k * OS);
            }
        }
        pb += 90;
        wptr = wnext;
    }
}

// ---------------- SMEM layout (floats; planes = 180 floats/cp) ----------------
//   h0P @ 0     : 5760     h1P @ 5760 : 5760      (phase A: xinHalf 64cp = 11520)
//   gsm @ 11520 : 256*50 = 12800                  (phase A: xoutP 64cp = 11520)
//   vtxP@ 24320 : 180      vfP @ 24500 : 180      lg @ 24680 : 52
#define SM_H0   0
#define SM_H1   5760
#define SM_G    11520
#define SM_VTX  24320
#define SM_VF   24500
#define SM_LG   24680
#define SMEM_FLOATS 24736

#define NT 256

__global__ __launch_bounds__(NT, 2)
void polyrnn_main(const float* __restrict__ x, const int* __restrict__ first_vertex,
                  const float* __restrict__ b0, const float* __restrict__ b1,
                  const float* __restrict__ bcx0, const float* __restrict__ bch0,
                  const float* __restrict__ bcx1, const float* __restrict__ bch1,
                  const float* __restrict__ fcw, const float* __restrict__ fcb,
                  float* __restrict__ out)
{
    extern __shared__ float sm[];
    float* h0P   = sm + SM_H0;
    float* h1P   = sm + SM_H1;
    float* gsm   = sm + SM_G;
    float* vtxP  = sm + SM_VTX;
    float* vfP   = sm + SM_VF;
    float* lg    = sm + SM_LG;
    float* xin   = sm;            // phase A: streamed 64-cp input half / x2P
    float* xoutP = sm + SM_G;     // phase A: conv0 output (64 cp)

    const int s   = blockIdx.x;
    const int tid = threadIdx.x;

    // ---- 1: zero ALL smem (borders must be 0) ----
    for (int i = tid; i < SMEM_FLOATS; i += NT) sm[i] = 0.0f;
    __syncthreads();

    const float* xs = x + (size_t)s * (256 * 49);
    const int o7 = tid & 127, q = tid >> 7;   // q=0: rows 0-3 (28 acc), q=1: rows 4-6 (21)

    // ---- 2+3: conv0 (256->128) + ReLU, streamed over two 64-cp input halves ----
    {
        const unsigned long long binit = pack2(b0[o7], 0.0f);
        unsigned long long a0[28];
#pragma unroll
        for (int i = 0; i < 28; ++i) a0[i] = binit;

        for (int i = tid; i < 128 * 49; i += NT) {
            int c = i / 49, p = i % 49;
            xin[(c >> 1) * 180 + pidx(p) + (c & 1)] = xs[i];
        }
        __syncthreads();
        if (q == 0) conv_rm<4, 0, 128>(g_p_conv0, 64, xin, o7, a0);
        else        conv_rm<3, 4, 128>(g_p_conv0, 64, xin, o7, a0);
        __syncthreads();

        for (int i = tid; i < 128 * 49; i += NT) {
            int c = i / 49, p = i % 49;
            xin[(c >> 1) * 180 + pidx(p) + (c & 1)] = xs[128 * 49 + i];
        }
        __syncthreads();
        if (q == 0) conv_rm<4, 0, 128>(g_p_conv0 + 64 * 9 * 128, 64, xin, o7, a0);
        else        conv_rm<3, 4, 128>(g_p_conv0 + 64 * 9 * 128, 64, xin, o7, a0);

        const int nr = q ? 3 : 4, r0 = q ? 4 : 0;
        for (int lr = 0; lr < nr; ++lr)
#pragma unroll
            for (int xq = 0; xq < 7; ++xq)
                xoutP[(o7 >> 1) * 180 + pidx((r0 + lr) * 7 + xq) + (o7 & 1)] =
                    fmaxf(fold2(a0[lr * 7 + xq]), 0.0f);
    }
    __syncthreads();

    // ---- 4: conv1 (128->128) + ReLU -> x2P (xin region) ----
    {
        const unsigned long long binit = pack2(b1[o7], 0.0f);
        unsigned long long a1[28];
#pragma unroll
        for (int i = 0; i < 28; ++i) a1[i] = binit;
        if (q == 0) conv_rm<4, 0, 128>(g_p_conv1, 64, xoutP, o7, a1);
        else        conv_rm<3, 4, 128>(g_p_conv1, 64, xoutP, o7, a1);
        __syncthreads();
        const int nr = q ? 3 : 4, r0 = q ? 4 : 0;
        for (int lr = 0; lr < nr; ++lr)
#pragma unroll
            for (int xq = 0; xq < 7; ++xq)
                xin[(o7 >> 1) * 180 + pidx((r0 + lr) * 7 + xq) + (o7 & 1)] =
                    fmaxf(fold2(a1[lr * 7 + xq]), 0.0f);
    }
    // ---- 5: v_first plane (vfP zeroed at start) ----
    if (tid == 0) {
        int v = first_vertex[s];             // [0,48]
        vfP[pidx(v) + 0] = 1.0f;             // (v_first, 0) pair
    }
    __syncthreads();

    // ---- 6: const gates: g_gxc = bias_g0 + conv(x2P cps0..63 + vfP; cx0), transposed ----
    {
        const float bg0 = bcx0[tid] + bch0[tid];
        float* gx = g_gxc + (size_t)s * 12544;
        {
            unsigned long long a[28];
            const unsigned long long binit = pack2(bg0, 0.0f);
#pragma unroll
            for (int i = 0; i < 28; ++i) a[i] = binit;
            conv_rm<4, 0, 256>(g_p_cx0, 64, xin, tid, a);
            conv_rm<4, 0, 256>(g_p_cx0 + 64 * 9 * 256, 1, vfP, tid, a);
#pragma unroll
            for (int i = 0; i < 28; ++i) gx[i * 256 + tid] = fold2(a[i]);
        }
        {
            unsigned long long a[21];
#pragma unroll
            for (int i = 0; i < 21; ++i) a[i] = pack2(0.0f, 0.0f);
            conv_rm<3, 4, 256>(g_p_cx0, 64, xin, tid, a);
            conv_rm<3, 4, 256>(g_p_cx0 + 64 * 9 * 256, 1, vfP, tid, a);
#pragma unroll
            for (int i = 0; i < 21; ++i) gx[(28 + i) * 256 + tid] = bg0 + fold2(a[i]);
        }
    }
    __syncthreads();

    // ---- 7: zero h planes (x2P junk); init v_p1 = v_first one-hot ----
    for (int i = tid; i < 11520; i += NT) sm[i] = 0.0f;
    if (tid < 180) vtxP[tid] = 0.0f;
    __syncthreads();
    if (tid == 0) {
        int v = first_vertex[s];
        vtxP[pidx(v) + 1] = 1.0f;            // (v_p2, v_p1): hi lane = v_p1
    }
    __syncthreads();

    const int warp = tid >> 5, lane = tid & 31;
    // warp-per-gate channel remap: each warp owns one gate type (warp-uniform activation)
    const int gate = warp & 3;                            // 0:i 1:f 2:g 3:o
    const int o_r  = (gate << 6) | ((warp >> 2) << 5) | lane;  // gate*64 + half*32 + lane
    const float bias_g1 = bcx1[o_r] + bch1[o_r];
    const float2* cx0_dyn = g_p_cx0 + 65 * 9 * 256;       // dynamic (v_p2, v_p1) pair weights
    const float* gx = g_gxc + (size_t)s * 12544;
    float* cg0 = g_c + (size_t)s * 6272;
    float* cg1 = cg0 + 3136;

    for (int t = 0; t < STEPS; ++t) {
        // ---- layer0 gates: gxc + conv(vtxP; cx0_dyn) + conv(h0P; ch0) ----
        // activation applied in-epilogue, warp-uniform; t=0 skip of zero-plane conv
        // is bit-identical (fma(w,0,a)==a)
        {
            unsigned long long a[28];
#pragma unroll
            for (int i = 0; i < 28; ++i) a[i] = pack2(gx[i * 256 + o_r], 0.0f);
            conv_rm<4, 0, 256>(cx0_dyn, 1, vtxP, o_r, a);
            if (t > 0) conv_rm<4, 0, 256>(g_p_ch0, 32, h0P, o_r, a);
#pragma unroll
            for (int i = 0; i < 14; ++i) {
                float v0 = gact(gate, fold2(a[2 * i]));
                float v1 = gact(gate, fold2(a[2 * i + 1]));
                *(unsigned long long*)(gsm + o_r * 50 + 2 * i) = pack2(v0, v1);
            }
        }
        {
            unsigned long long a[21];
#pragma unroll
            for (int i = 0; i < 21; ++i) a[i] = pack2(gx[(28 + i) * 256 + o_r], 0.0f);
            conv_rm<3, 4, 256>(cx0_dyn, 1, vtxP, o_r, a);
            if (t > 0) conv_rm<3, 4, 256>(g_p_ch0, 32, h0P, o_r, a);
#pragma unroll
            for (int i = 0; i < 10; ++i) {
                float v0 = gact(gate, fold2(a[2 * i]));
                float v1 = gact(gate, fold2(a[2 * i + 1]));
                *(unsigned long long*)(gsm + o_r * 50 + 28 + 2 * i) = pack2(v0, v1);
            }
            gsm[o_r * 50 + 48] = gact(gate, fold2(a[20]));
        }
        __syncthreads();

        // ---- LSTM0: gates pre-activated; only tanh(cy) remains ----
        for (int i = tid; i < 3136; i += NT) {
            int c = i / 49, p = i - c * 49;
            float ig = gsm[c * 50 + p];
            float fg = gsm[(c + 64) * 50 + p];
            float gg = gsm[(c + 128) * 50 + p];
            float og = gsm[(c + 192) * 50 + p];
            float cprev = (t == 0) ? 0.0f : cg0[i];
            float cy = fg * cprev + ig * gg;
            cg0[i] = cy;
            h0P[(c >> 1) * 180 + pidx(p) + (c & 1)] = og * tanhf(cy);
        }
        __syncthreads();

        // ---- layer1 gates: conv(h0P; cx1) + conv(h1P; ch1) ----
        {
            unsigned long long a[28];
            const unsigned long long binit = pack2(bias_g1, 0.0f);
#pragma unroll
            for (int i = 0; i < 28; ++i) a[i] = binit;
            conv_rm<4, 0, 256>(g_p_cx1, 32, h0P, o_r, a);
            if (t > 0) conv_rm<4, 0, 256>(g_p_ch1, 32, h1P, o_r, a);
#pragma unroll
            for (int i = 0; i < 14; ++i) {
                float v0 = gact(gate, fold2(a[2 * i]));
                float v1 = gact(gate, fold2(a[2 * i + 1]));
                *(unsigned long long*)(gsm + o_r * 50 + 2 * i) = pack2(v0, v1);
            }
        }
        {
            unsigned long long a[21];
            const unsigned long long binit = pack2(bias_g1, 0.0f);
#pragma unroll
            for (int i = 0; i < 21; ++i) a[i] = binit;
            conv_rm<3, 4, 256>(g_p_cx1, 32, h0P, o_r, a);
            if (t > 0) conv_rm<3, 4, 256>(g_p_ch1, 32, h1P, o_r, a);
#pragma unroll
            for (int i = 0; i < 10; ++i) {
                float v0 = gact(gate, fold2(a[2 * i]));
                float v1 = gact(gate, fold2(a[2 * i + 1]));
                *(unsigned long long*)(gsm + o_r * 50 + 28 + 2 * i) = pack2(v0, v1);
            }
            gsm[o_r * 50 + 48] = gact(gate, fold2(a[20]));
        }
        __syncthreads();

        // ---- LSTM1 ----
        for (int i = tid; i < 3136; i += NT) {
            int c = i / 49, p = i - c * 49;
            float ig = gsm[c * 50 + p];
            float fg = gsm[(c + 64) * 50 + p];
            float gg = gsm[(c + 128) * 50 + p];
            float og = gsm[(c + 192) * 50 + p];
            float cprev = (t == 0) ? 0.0f : cg1[i];
            float cy = fg * cprev + ig * gg;
            cg1[i] = cy;
            h1P[(c >> 1) * 180 + pidx(p) + (c & 1)] = og * tanhf(cy);
        }
        __syncthreads();

        // ---- fc: logits[50] over 8 warps; 4 independent FFMA2 chains ----
        for (int o = warp; o < 50; o += 8) {
            unsigned long long s0 = pack2(0.0f, 0.0f), s1 = s0, s2 = s0, s3 = s0;
            const unsigned long long* wr = (const unsigned long long*)g_p_fc + o * 1568;
            const unsigned long long* h1u = (const unsigned long long*)h1P;
            int cp = 0, p = lane, e = lane;
#pragma unroll 1
            for (int blk = 0; blk < 12; ++blk) {     // 48 of 49 iterations, 4 chains
                ffma2(s0, __ldg(wr + e), h1u[cp * 90 + pidx64(p)]);
                e += 32; p += 32; if (p >= 49) { p -= 49; ++cp; }
                ffma2(s1, __ldg(wr + e), h1u[cp * 90 + pidx64(p)]);
                e += 32; p += 32; if (p >= 49) { p -= 49; ++cp; }
                ffma2(s2, __ldg(wr + e), h1u[cp * 90 + pidx64(p)]);
                e += 32; p += 32; if (p >= 49) { p -= 49; ++cp; }
                ffma2(s3, __ldg(wr + e), h1u[cp * 90 + pidx64(p)]);
                e += 32; p += 32; if (p >= 49) { p -= 49; ++cp; }
            }
            ffma2(s0, __ldg(wr + e), h1u[cp * 90 + pidx64(p)]);   // iteration 49
            float ssum = (fold2(s0) + fold2(s1)) + (fold2(s2) + fold2(s3));
#pragma unroll
            for (int d = 16; d; d >>= 1) ssum += __shfl_down_sync(0xffffffffu, ssum, d);
            if (lane == 0) lg[o] = ssum + fcb[o];
        }
        __syncthreads();

        // ---- emit; fused argmax + feedback in warp 0 (first-max-wins) ----
        if (tid < 50) out[((size_t)s * STEPS + t) * 50 + tid] = lg[tid];
        if (warp == 0) {
            float bv = lg[lane];
            int bi = lane;
            float v2 = (lane < 18) ? lg[32 + lane] : -3.402823466e38f;
            if (v2 > bv) { bv = v2; bi = 32 + lane; }
#pragma unroll
            for (int d = 16; d; d >>= 1) {
                float ov = __shfl_down_sync(0xffffffffu, bv, d);
                int   oi = __shfl_down_sync(0xffffffffu, bi, d);
                if (ov > bv || (ov == bv && oi < bi)) { bv = ov; bi = oi; }
            }
            bi = __shfl_sync(0xffffffffu, bi, 0);
            for (int p4 = lane; p4 < 49; p4 += 32) {
                int a2 = pidx(p4);
                vtxP[a2 + 0] = vtxP[a2 + 1];
                vtxP[a2 + 1] = (bi == p4) ? 1.0f : 0.0f;
            }
        }
        __syncthreads();
    }
}

extern "C" void kernel_launch(void* const* d_in, const int* in_sizes, int n_in,
                              void* d_out, int out_size)
{
    const float* x    = (const float*)d_in[0];
    const int*   fv   = (const int*)  d_in[1];
    const float* w0   = (const float*)d_in[2];
    const float* b0   = (const float*)d_in[3];
    const float* w1   = (const float*)d_in[4];
    const float* b1   = (const float*)d_in[5];
    const float* wcx0 = (const float*)d_in[6];
    const float* bcx0 = (const float*)d_in[7];
    const float* wch0 = (const float*)d_in[8];
    const float* bch0 = (const float*)d_in[9];
    const float* wcx1 = (const float*)d_in[10];
    const float* bcx1 = (const float*)d_in[11];
    const float* wch1 = (const float*)d_in[12];
    const float* bch1 = (const float*)d_in[13];
    const float* fcw  = (const float*)d_in[14];
    const float* fcb  = (const float*)d_in[15];
    float* out = (float*)d_out;

    const int n = in_sizes[1];  // batch (2048)

    const int total = 128 * 9 * 128 + 64 * 9 * 128 + 66 * 9 * 256 + 3 * 32 * 9 * 256
                    + 50 * 1568;
    pack_weights<<<(total + 255) / 256, 256>>>(w0, w1, wcx0, wch0, wcx1, wch1, fcw);

    const int smem_bytes = SMEM_FLOATS * 4;
    cudaFuncSetAttribute(polyrnn_main, cudaFuncAttributeMaxDynamicSharedMemorySize, smem_bytes);
    polyrnn_main<<<n, NT, smem_bytes>>>(x, fv, b0, b1, bcx0, bch0, bcx1, bch1, fcw, fcb, out);
}